// round 9
// baseline (speedup 1.0000x reference)
#include <cuda_runtime.h>
#include <cuda_bf16.h>
#include <math.h>

#define DDIM 128
#define NMAX 50000
#define EMAX 800000
#define ASTR 36            // bf16x2 stride per row (32 data + 4 pad), %32==4 -> conflict-free
#define KC   64            // k-chunk (32 bf16x2)
#define CAP  64            // ELL capacity per node (Poisson(16): max deg ~45)
#define OVFMAX 65536
#define NTILES_MAX 400

// Scratch (alloc-free rule: __device__ globals)
__device__ float g_support[(size_t)NMAX * DDIM];
__device__ float g_agg[(size_t)NMAX * DDIM];
__device__ int   g_deg[NMAX];
__device__ uint2 g_ell[(size_t)NMAX * CAP];   // (src, val_bits) per slot
__device__ int   g_ovf_cnt;
__device__ uint4 g_ovf[OVFMAX];               // (src, dst, val_bits, -)
__device__ int   g_tile_cnt[NTILES_MAX];      // gather-done counters per 128-row tile
// pre-split weights, bf16x2 hi/lo, layout [n][k2] (k2 = k/2), 64 k2 per row
__device__ unsigned gW0h[DDIM * (DDIM / 2)], gW0l[DDIM * (DDIM / 2)];
__device__ unsigned gW1h[DDIM * (DDIM / 2)], gW1l[DDIM * (DDIM / 2)];

// ---------------------------------------------------------------------------
__device__ __forceinline__ void split_pair(float x, float y, unsigned& hp, unsigned& lp) {
    __nv_bfloat16 hx = __float2bfloat16_rn(x);
    __nv_bfloat16 hy = __float2bfloat16_rn(y);
    __nv_bfloat16 lx = __float2bfloat16_rn(x - __bfloat162float(hx));
    __nv_bfloat16 ly = __float2bfloat16_rn(y - __bfloat162float(hy));
    hp = (unsigned)__bfloat16_as_ushort(hx) | ((unsigned)__bfloat16_as_ushort(hy) << 16);
    lp = (unsigned)__bfloat16_as_ushort(lx) | ((unsigned)__bfloat16_as_ushort(ly) << 16);
}

__device__ __forceinline__ void mma_bf16(float c[4], const unsigned a[4],
                                         unsigned b0, unsigned b1) {
    asm volatile(
        "mma.sync.aligned.m16n8k16.row.col.f32.bf16.bf16.f32 "
        "{%0,%1,%2,%3}, {%4,%5,%6,%7}, {%8,%9}, {%0,%1,%2,%3};"
        : "+f"(c[0]), "+f"(c[1]), "+f"(c[2]), "+f"(c[3])
        : "r"(a[0]), "r"(a[1]), "r"(a[2]), "r"(a[3]), "r"(b0), "r"(b1));
}

// ---------------------------------------------------------------------------
// Init: zero deg / ovf / tile counters, pre-split both weight matrices.
// ---------------------------------------------------------------------------
__global__ void init_kernel(int n, const float* __restrict__ W_gc,
                            const float* __restrict__ W2) {
    int i = blockIdx.x * blockDim.x + threadIdx.x;
    if (i < n) g_deg[i] = 0;
    if (i < NTILES_MAX) g_tile_cnt[i] = 0;
    if (i == 0) g_ovf_cnt = 0;
    if (i < DDIM * (DDIM / 2)) {                 // W_gc: [k][n] -> [n][k2]
        int nn = i & (DDIM - 1), k2 = i >> 7;
        float w0 = __ldg(W_gc + (size_t)(2 * k2) * DDIM + nn);
        float w1 = __ldg(W_gc + (size_t)(2 * k2 + 1) * DDIM + nn);
        unsigned hp, lp;
        split_pair(w0, w1, hp, lp);
        gW0h[nn * (DDIM / 2) + k2] = hp;
        gW0l[nn * (DDIM / 2) + k2] = lp;
    } else if (i < 2 * DDIM * (DDIM / 2)) {      // W2: [n][k] -> [n][k2]
        int j = i - DDIM * (DDIM / 2);
        int nn = j >> 6, k2 = j & 63;
        float w0 = __ldg(W2 + (size_t)nn * DDIM + 2 * k2);
        float w1 = __ldg(W2 + (size_t)nn * DDIM + 2 * k2 + 1);
        unsigned hp, lp;
        split_pair(w0, w1, hp, lp);
        gW1h[nn * (DDIM / 2) + k2] = hp;
        gW1l[nn * (DDIM / 2) + k2] = lp;
    }
}

// ---------------------------------------------------------------------------
// GEMM0 tile body (support = X @ W_gc + b). Same as round 7.
// ---------------------------------------------------------------------------
__device__ __forceinline__ void gemm0_tile(const float* __restrict__ X,
                                           const float* __restrict__ bias,
                                           float* __restrict__ out,
                                           int n, int tileIdx, unsigned* smu) {
    unsigned* Ah = smu;
    unsigned* Al = smu + 128 * ASTR;
    unsigned* Bh = smu + 2 * 128 * ASTR;
    unsigned* Bl = smu + 3 * 128 * ASTR;

    const int tid  = threadIdx.x;
    const int lane = tid & 31;
    const int wid  = tid >> 5;
    const int gid  = lane >> 2;
    const int tg   = lane & 3;
    const int wm   = wid >> 1;
    const int wn   = wid & 1;
    const int rb   = tileIdx * 128;

    float acc[2][8][4];
#pragma unroll
    for (int mt = 0; mt < 2; mt++)
#pragma unroll
        for (int nt = 0; nt < 8; nt++)
#pragma unroll
            for (int j = 0; j < 4; j++) acc[mt][nt][j] = 0.f;

#pragma unroll
    for (int kc0 = 0; kc0 < DDIM; kc0 += KC) {
        {
            int rl = tid >> 4;
            int c4 = (tid & 15) * 4;
#pragma unroll
            for (int i = 0; i < 8; i++) {
                int row  = rl + 16 * i;
                int grow = rb + row;
                float4 v = make_float4(0.f, 0.f, 0.f, 0.f);
                if (grow < n)
                    v = *(const float4*)(X + (size_t)grow * DDIM + kc0 + c4);
                unsigned h0, l0, h1, l1;
                split_pair(v.x, v.y, h0, l0);
                split_pair(v.z, v.w, h1, l1);
                int sa = row * ASTR + (c4 >> 1);
                *(uint2*)(Ah + sa) = make_uint2(h0, h1);
                *(uint2*)(Al + sa) = make_uint2(l0, l1);
            }
        }
        {
            int nn   = tid >> 1;
            int half = tid & 1;
            int gb = nn * (DDIM / 2) + (kc0 >> 1) + half * 16;
            int sb = nn * ASTR + half * 16;
#pragma unroll
            for (int j = 0; j < 4; j++) {
                *(uint4*)(Bh + sb + 4 * j) = *(const uint4*)(gW0h + gb + 4 * j);
                *(uint4*)(Bl + sb + 4 * j) = *(const uint4*)(gW0l + gb + 4 * j);
            }
        }
        __syncthreads();

#pragma unroll
        for (int ks = 0; ks < 4; ks++) {
            int kb = ks * 8;
            unsigned ah[2][4], al[2][4];
#pragma unroll
            for (int mt = 0; mt < 2; mt++) {
                int base = (wm * 32 + mt * 16 + gid) * ASTR + kb + tg;
                ah[mt][0] = Ah[base];
                ah[mt][1] = Ah[base + 8 * ASTR];
                ah[mt][2] = Ah[base + 4];
                ah[mt][3] = Ah[base + 8 * ASTR + 4];
                al[mt][0] = Al[base];
                al[mt][1] = Al[base + 8 * ASTR];
                al[mt][2] = Al[base + 4];
                al[mt][3] = Al[base + 8 * ASTR + 4];
            }
#pragma unroll
            for (int nt = 0; nt < 8; nt++) {
                int nb = (wn * 64 + nt * 8 + gid) * ASTR + kb + tg;
                unsigned bh0 = Bh[nb], bh1 = Bh[nb + 4];
                unsigned bl0 = Bl[nb], bl1 = Bl[nb + 4];
#pragma unroll
                for (int mt = 0; mt < 2; mt++) {
                    mma_bf16(acc[mt][nt], ah[mt], bh0, bh1);
                    mma_bf16(acc[mt][nt], ah[mt], bl0, bl1);
                    mma_bf16(acc[mt][nt], al[mt], bh0, bh1);
                }
            }
        }
        __syncthreads();
    }

#pragma unroll
    for (int mt = 0; mt < 2; mt++)
#pragma unroll
        for (int h = 0; h < 2; h++) {
            int row = rb + wm * 32 + mt * 16 + h * 8 + gid;
            if (row < n) {
#pragma unroll
                for (int nt = 0; nt < 8; nt++) {
                    int col = wn * 64 + nt * 8 + tg * 2;
                    float b0 = __ldg(bias + col), b1 = __ldg(bias + col + 1);
                    float2 v = make_float2(acc[mt][nt][2 * h] + b0,
                                           acc[mt][nt][2 * h + 1] + b1);
                    *(float2*)(out + (size_t)row * DDIM + col) = v;
                }
            }
        }
}

// ---------------------------------------------------------------------------
// Fused kernel 1: gemm0 tiles and ELL-fill chunks interleaved (round 7).
// ---------------------------------------------------------------------------
__global__ void __launch_bounds__(256, 2)
fused0_kernel(const float* __restrict__ x, const float* __restrict__ b_gc,
              const int* __restrict__ src, const int* __restrict__ dst,
              const float* __restrict__ vals,
              int n, int e, int gblocks, int fillchunks) {
    extern __shared__ unsigned smu[];
    int b  = blockIdx.x;
    int g3 = b / 3, r = b % 3;
    if (r == 0) {
        if (g3 < gblocks)
            gemm0_tile(x, b_gc, g_support, n, g3, smu);
        return;
    }
    int fb = g3 * 2 + (r - 1);
    if (fb >= fillchunks) return;
    int base = fb * 1024 + threadIdx.x * 4;
#pragma unroll
    for (int j = 0; j < 4; j++) {
        int i = base + j;
        if (i >= e) break;
        int d = __ldg(dst + i);
        int s = __ldg(src + i);
        float v = __ldg(vals + i);
        int slot = atomicAdd(&g_deg[d], 1);
        if (slot < CAP) {
            g_ell[(size_t)d * CAP + slot] = make_uint2((unsigned)s, __float_as_uint(v));
        } else {
            int o = atomicAdd(&g_ovf_cnt, 1);
            if (o < OVFMAX)
                g_ovf[o] = make_uint4((unsigned)s, (unsigned)d, __float_as_uint(v), 0u);
        }
    }
}

// ---------------------------------------------------------------------------
// Pipe kernel: per tile t, 16 gather CTAs (blocks 17t+0..15, one warp/node)
// + 1 gemm CTA (block 17t+16) that waits on the tile counter then runs the
// W2^T GEMM + rownorm. Dependencies point only to lower block indices ->
// deadlock-free under in-order dispatch.
// ---------------------------------------------------------------------------
__global__ void __launch_bounds__(256, 2)
pipe_kernel(const float* __restrict__ b2, float* __restrict__ out,
            int n, int tiles) {
    extern __shared__ unsigned smu[];
    const int b = blockIdx.x;
    const int t = b / 17;
    const int r = b - t * 17;
    if (t >= tiles) return;
    const int tid  = threadIdx.x;
    const int lane = tid & 31;
    const int wid  = tid >> 5;

    if (r < 16) {
        // ---------------- gather role: node = t*128 + r*8 + wid ----------------
        int node = t * 128 + r * 8 + wid;
        if (node < n) {
            int raw = __ldg(&g_deg[node]);
            int cnt = min(raw, CAP);
            const uint4* el4 = (const uint4*)(g_ell + (size_t)node * CAP);
            float4 acc = make_float4(0.f, 0.f, 0.f, 0.f);
            int nq = cnt >> 2;
            for (int q = 0; q < nq; q++) {
                uint4 m0 = __ldg(el4 + 2 * q);
                uint4 m1 = __ldg(el4 + 2 * q + 1);
                float4 s0 = ((const float4*)(g_support + (size_t)m0.x * DDIM))[lane];
                float4 s1 = ((const float4*)(g_support + (size_t)m0.z * DDIM))[lane];
                float4 s2 = ((const float4*)(g_support + (size_t)m1.x * DDIM))[lane];
                float4 s3 = ((const float4*)(g_support + (size_t)m1.z * DDIM))[lane];
                float v0 = __uint_as_float(m0.y), v1 = __uint_as_float(m0.w);
                float v2 = __uint_as_float(m1.y), v3 = __uint_as_float(m1.w);
                acc.x = fmaf(s0.x, v0, acc.x); acc.y = fmaf(s0.y, v0, acc.y);
                acc.z = fmaf(s0.z, v0, acc.z); acc.w = fmaf(s0.w, v0, acc.w);
                acc.x = fmaf(s1.x, v1, acc.x); acc.y = fmaf(s1.y, v1, acc.y);
                acc.z = fmaf(s1.z, v1, acc.z); acc.w = fmaf(s1.w, v1, acc.w);
                acc.x = fmaf(s2.x, v2, acc.x); acc.y = fmaf(s2.y, v2, acc.y);
                acc.z = fmaf(s2.z, v2, acc.z); acc.w = fmaf(s2.w, v2, acc.w);
                acc.x = fmaf(s3.x, v3, acc.x); acc.y = fmaf(s3.y, v3, acc.y);
                acc.z = fmaf(s3.z, v3, acc.z); acc.w = fmaf(s3.w, v3, acc.w);
            }
            for (int i = nq * 4; i < cnt; i++) {
                uint2 m = __ldg(g_ell + (size_t)node * CAP + i);
                float v = __uint_as_float(m.y);
                float4 s = ((const float4*)(g_support + (size_t)m.x * DDIM))[lane];
                acc.x = fmaf(s.x, v, acc.x); acc.y = fmaf(s.y, v, acc.y);
                acc.z = fmaf(s.z, v, acc.z); acc.w = fmaf(s.w, v, acc.w);
            }
            if (raw > CAP) {        // ~never
                int c = min(g_ovf_cnt, OVFMAX);
                for (int i = 0; i < c; i++) {
                    uint4 m = g_ovf[i];
                    if (m.y == (unsigned)node) {
                        float v = __uint_as_float(m.z);
                        float4 s = ((const float4*)(g_support + (size_t)m.x * DDIM))[lane];
                        acc.x = fmaf(s.x, v, acc.x); acc.y = fmaf(s.y, v, acc.y);
                        acc.z = fmaf(s.z, v, acc.z); acc.w = fmaf(s.w, v, acc.w);
                    }
                }
            }
            *(float4*)(g_agg + (size_t)node * DDIM + lane * 4) = acc;
        }
        __syncthreads();
        if (tid == 0) {
            __threadfence();                       // publish stores gpu-wide
            atomicAdd(&g_tile_cnt[t], 1);
        }
        return;
    }

    // ---------------- gemm role: wait for tile's 16 gather CTAs ----------------
    if (tid == 0) {
        volatile int* p = &g_tile_cnt[t];
        while (*p < 16) __nanosleep(64);
        __threadfence();                           // acquire
    }
    __syncthreads();

    unsigned* Ah = smu;
    unsigned* Al = smu + 128 * ASTR;
    unsigned* Bh = smu + 2 * 128 * ASTR;
    unsigned* Bl = smu + 3 * 128 * ASTR;

    const int gid = lane >> 2;
    const int tg  = lane & 3;
    const int wm  = wid >> 1;
    const int wn  = wid & 1;
    const int rb  = t * 128;

    float acc[2][8][4];
#pragma unroll
    for (int mt = 0; mt < 2; mt++)
#pragma unroll
        for (int nt = 0; nt < 8; nt++)
#pragma unroll
            for (int j = 0; j < 4; j++) acc[mt][nt][j] = 0.f;

#pragma unroll
    for (int kc0 = 0; kc0 < DDIM; kc0 += KC) {
        {
            int rl = tid >> 4;
            int c4 = (tid & 15) * 4;
#pragma unroll
            for (int i = 0; i < 8; i++) {
                int row  = rl + 16 * i;
                int grow = rb + row;
                float4 v = make_float4(0.f, 0.f, 0.f, 0.f);
                if (grow < n)
                    v = __ldcg((const float4*)(g_agg + (size_t)grow * DDIM + kc0 + c4));
                v.x = fmaxf(v.x, 0.f); v.y = fmaxf(v.y, 0.f);
                v.z = fmaxf(v.z, 0.f); v.w = fmaxf(v.w, 0.f);
                unsigned h0, l0, h1, l1;
                split_pair(v.x, v.y, h0, l0);
                split_pair(v.z, v.w, h1, l1);
                int sa = row * ASTR + (c4 >> 1);
                *(uint2*)(Ah + sa) = make_uint2(h0, h1);
                *(uint2*)(Al + sa) = make_uint2(l0, l1);
            }
        }
        {
            int nn   = tid >> 1;
            int half = tid & 1;
            int gb = nn * (DDIM / 2) + (kc0 >> 1) + half * 16;
            int sb = nn * ASTR + half * 16;
#pragma unroll
            for (int j = 0; j < 4; j++) {
                *(uint4*)(Bh + sb + 4 * j) = *(const uint4*)(gW1h + gb + 4 * j);
                *(uint4*)(Bl + sb + 4 * j) = *(const uint4*)(gW1l + gb + 4 * j);
            }
        }
        __syncthreads();

#pragma unroll
        for (int ks = 0; ks < 4; ks++) {
            int kb = ks * 8;
            unsigned ah[2][4], al[2][4];
#pragma unroll
            for (int mt = 0; mt < 2; mt++) {
                int base = (wm * 32 + mt * 16 + gid) * ASTR + kb + tg;
                ah[mt][0] = Ah[base];
                ah[mt][1] = Ah[base + 8 * ASTR];
                ah[mt][2] = Ah[base + 4];
                ah[mt][3] = Ah[base + 8 * ASTR + 4];
                al[mt][0] = Al[base];
                al[mt][1] = Al[base + 8 * ASTR];
                al[mt][2] = Al[base + 4];
                al[mt][3] = Al[base + 8 * ASTR + 4];
            }
#pragma unroll
            for (int nt = 0; nt < 8; nt++) {
                int nb = (wn * 64 + nt * 8 + gid) * ASTR + kb + tg;
                unsigned bh0 = Bh[nb], bh1 = Bh[nb + 4];
                unsigned bl0 = Bl[nb], bl1 = Bl[nb + 4];
#pragma unroll
                for (int mt = 0; mt < 2; mt++) {
                    mma_bf16(acc[mt][nt], ah[mt], bh0, bh1);
                    mma_bf16(acc[mt][nt], ah[mt], bl0, bl1);
                    mma_bf16(acc[mt][nt], al[mt], bh0, bh1);
                }
            }
        }
        __syncthreads();
    }

    // epilogue: bias + rownorm
    float* red = (float*)smu;
#pragma unroll
    for (int mt = 0; mt < 2; mt++)
#pragma unroll
        for (int nt = 0; nt < 8; nt++) {
            int col = wn * 64 + nt * 8 + tg * 2;
            float b0 = __ldg(b2 + col), b1 = __ldg(b2 + col + 1);
            acc[mt][nt][0] += b0; acc[mt][nt][1] += b1;
            acc[mt][nt][2] += b0; acc[mt][nt][3] += b1;
        }
#pragma unroll
    for (int mt = 0; mt < 2; mt++)
#pragma unroll
        for (int h = 0; h < 2; h++) {
            float ss = 0.f;
#pragma unroll
            for (int nt = 0; nt < 8; nt++) {
                ss = fmaf(acc[mt][nt][2 * h], acc[mt][nt][2 * h], ss);
                ss = fmaf(acc[mt][nt][2 * h + 1], acc[mt][nt][2 * h + 1], ss);
            }
            ss += __shfl_xor_sync(0xffffffffu, ss, 1);
            ss += __shfl_xor_sync(0xffffffffu, ss, 2);
            if (tg == 0)
                red[(wm * 32 + mt * 16 + h * 8 + gid) * 2 + wn] = ss;
        }
    __syncthreads();
#pragma unroll
    for (int mt = 0; mt < 2; mt++)
#pragma unroll
        for (int h = 0; h < 2; h++) {
            int rl  = wm * 32 + mt * 16 + h * 8 + gid;
            int row = rb + rl;
            float inv = 1.f / sqrtf(red[rl * 2] + red[rl * 2 + 1]);
            if (row < n) {
#pragma unroll
                for (int nt = 0; nt < 8; nt++) {
                    int col = wn * 64 + nt * 8 + tg * 2;
                    float2 v = make_float2(acc[mt][nt][2 * h] * inv,
                                           acc[mt][nt][2 * h + 1] * inv);
                    *(float2*)(out + (size_t)row * DDIM + col) = v;
                }
            }
        }
}

// ---------------------------------------------------------------------------
extern "C" void kernel_launch(void* const* d_in, const int* in_sizes, int n_in,
                              void* d_out, int out_size) {
    const float* x    = (const float*)d_in[0];
    const float* vals = (const float*)d_in[1];
    const float* W_gc = (const float*)d_in[2];
    const float* b_gc = (const float*)d_in[3];
    const float* W2   = (const float*)d_in[4];
    const float* b2   = (const float*)d_in[5];
    const int*   src  = (const int*)d_in[6];
    const int*   dst  = (const int*)d_in[7];

    const int n = in_sizes[0] / DDIM;
    const int e = in_sizes[1];

    const int smem = 4 * 128 * ASTR * 4;   // 73728 B
    cudaFuncSetAttribute(fused0_kernel,
                         cudaFuncAttributeMaxDynamicSharedMemorySize, smem);
    cudaFuncSetAttribute(pipe_kernel,
                         cudaFuncAttributeMaxDynamicSharedMemorySize, smem);

    // 1) init: zero deg/ovf/tile counters + pre-split weights
    int ithreads = n > 2 * DDIM * (DDIM / 2) ? n : 2 * DDIM * (DDIM / 2);
    init_kernel<<<(ithreads + 255) / 256, 256>>>(n, W_gc, W2);

    // 2) fused: gemm0 (support = x@W_gc + b_gc) || ELL fill
    int gblocks = (n + 127) / 128;
    int fillchunks = (e + 1023) / 1024;
    int gb2 = gblocks > (fillchunks + 1) / 2 ? gblocks : (fillchunks + 1) / 2;
    fused0_kernel<<<3 * gb2, 256, smem>>>(x, b_gc, src, dst, vals,
                                          n, e, gblocks, fillchunks);

    // 3) pipe: gather tiles + dependent gemm1 tiles in one grid
    pipe_kernel<<<17 * gblocks, 256, smem>>>(b2, (float*)d_out, n, gblocks);
}

// round 10
// speedup vs baseline: 1.2065x; 1.2065x over previous
#include <cuda_runtime.h>
#include <cuda_bf16.h>
#include <math.h>

#define DDIM 128
#define NMAX 50000
#define EMAX 800000
#define ASTR 36            // per-chunk bf16x2 stride (32 data + 4 pad), %32==4 -> conflict-free
#define AFSTR 68           // full-K bf16x2 stride (64 data + 4 pad), %32==4 -> conflict-free
#define KC   64            // k-chunk (32 bf16x2)
#define CAP  64            // ELL capacity per node (Poisson(16): max deg ~45)
#define OVFMAX 65536

// Scratch (alloc-free rule: __device__ globals)
__device__ float g_support[(size_t)NMAX * DDIM];
__device__ int   g_deg[NMAX];
__device__ uint2 g_ell[(size_t)NMAX * CAP];   // (src, val_bits) per slot
__device__ int   g_ovf_cnt;
__device__ uint4 g_ovf[OVFMAX];               // (src, dst, val_bits, -)
// pre-split weights, bf16x2 hi/lo, layout [n][k2] (k2 = k/2), 64 k2 per row
__device__ unsigned gW0h[DDIM * (DDIM / 2)], gW0l[DDIM * (DDIM / 2)];
__device__ unsigned gW1h[DDIM * (DDIM / 2)], gW1l[DDIM * (DDIM / 2)];

// ---------------------------------------------------------------------------
__device__ __forceinline__ void split_pair(float x, float y, unsigned& hp, unsigned& lp) {
    __nv_bfloat16 hx = __float2bfloat16_rn(x);
    __nv_bfloat16 hy = __float2bfloat16_rn(y);
    __nv_bfloat16 lx = __float2bfloat16_rn(x - __bfloat162float(hx));
    __nv_bfloat16 ly = __float2bfloat16_rn(y - __bfloat162float(hy));
    hp = (unsigned)__bfloat16_as_ushort(hx) | ((unsigned)__bfloat16_as_ushort(hy) << 16);
    lp = (unsigned)__bfloat16_as_ushort(lx) | ((unsigned)__bfloat16_as_ushort(ly) << 16);
}

__device__ __forceinline__ void mma_bf16(float c[4], const unsigned a[4],
                                         unsigned b0, unsigned b1) {
    asm volatile(
        "mma.sync.aligned.m16n8k16.row.col.f32.bf16.bf16.f32 "
        "{%0,%1,%2,%3}, {%4,%5,%6,%7}, {%8,%9}, {%0,%1,%2,%3};"
        : "+f"(c[0]), "+f"(c[1]), "+f"(c[2]), "+f"(c[3])
        : "r"(a[0]), "r"(a[1]), "r"(a[2]), "r"(a[3]), "r"(b0), "r"(b1));
}

__device__ __forceinline__ void fma4(float4& a, float4 s, float v) {
    a.x = fmaf(s.x, v, a.x); a.y = fmaf(s.y, v, a.y);
    a.z = fmaf(s.z, v, a.z); a.w = fmaf(s.w, v, a.w);
}

// ---------------------------------------------------------------------------
// Init: zero deg + ovf counter, pre-split both weight matrices.
// ---------------------------------------------------------------------------
__global__ void init_kernel(int n, const float* __restrict__ W_gc,
                            const float* __restrict__ W2) {
    int i = blockIdx.x * blockDim.x + threadIdx.x;
    if (i < n) g_deg[i] = 0;
    if (i == 0) g_ovf_cnt = 0;
    if (i < DDIM * (DDIM / 2)) {                 // W_gc: [k][n] -> [n][k2]
        int nn = i & (DDIM - 1), k2 = i >> 7;
        float w0 = __ldg(W_gc + (size_t)(2 * k2) * DDIM + nn);
        float w1 = __ldg(W_gc + (size_t)(2 * k2 + 1) * DDIM + nn);
        unsigned hp, lp;
        split_pair(w0, w1, hp, lp);
        gW0h[nn * (DDIM / 2) + k2] = hp;
        gW0l[nn * (DDIM / 2) + k2] = lp;
    } else if (i < 2 * DDIM * (DDIM / 2)) {      // W2: [n][k] -> [n][k2]
        int j = i - DDIM * (DDIM / 2);
        int nn = j >> 6, k2 = j & 63;
        float w0 = __ldg(W2 + (size_t)nn * DDIM + 2 * k2);
        float w1 = __ldg(W2 + (size_t)nn * DDIM + 2 * k2 + 1);
        unsigned hp, lp;
        split_pair(w0, w1, hp, lp);
        gW1h[nn * (DDIM / 2) + k2] = hp;
        gW1l[nn * (DDIM / 2) + k2] = lp;
    }
}

// ---------------------------------------------------------------------------
// GEMM0 tile body (support = X @ W_gc + b).
// ---------------------------------------------------------------------------
__device__ __forceinline__ void gemm0_tile(const float* __restrict__ X,
                                           const float* __restrict__ bias,
                                           float* __restrict__ out,
                                           int n, int tileIdx, unsigned* smu) {
    unsigned* Ah = smu;
    unsigned* Al = smu + 128 * ASTR;
    unsigned* Bh = smu + 2 * 128 * ASTR;
    unsigned* Bl = smu + 3 * 128 * ASTR;

    const int tid  = threadIdx.x;
    const int lane = tid & 31;
    const int wid  = tid >> 5;
    const int gid  = lane >> 2;
    const int tg   = lane & 3;
    const int wm   = wid >> 1;
    const int wn   = wid & 1;
    const int rb   = tileIdx * 128;

    float acc[2][8][4];
#pragma unroll
    for (int mt = 0; mt < 2; mt++)
#pragma unroll
        for (int nt = 0; nt < 8; nt++)
#pragma unroll
            for (int j = 0; j < 4; j++) acc[mt][nt][j] = 0.f;

#pragma unroll
    for (int kc0 = 0; kc0 < DDIM; kc0 += KC) {
        {
            int rl = tid >> 4;
            int c4 = (tid & 15) * 4;
#pragma unroll
            for (int i = 0; i < 8; i++) {
                int row  = rl + 16 * i;
                int grow = rb + row;
                float4 v = make_float4(0.f, 0.f, 0.f, 0.f);
                if (grow < n)
                    v = *(const float4*)(X + (size_t)grow * DDIM + kc0 + c4);
                unsigned h0, l0, h1, l1;
                split_pair(v.x, v.y, h0, l0);
                split_pair(v.z, v.w, h1, l1);
                int sa = row * ASTR + (c4 >> 1);
                *(uint2*)(Ah + sa) = make_uint2(h0, h1);
                *(uint2*)(Al + sa) = make_uint2(l0, l1);
            }
        }
        {
            int nn   = tid >> 1;
            int half = tid & 1;
            int gb = nn * (DDIM / 2) + (kc0 >> 1) + half * 16;
            int sb = nn * ASTR + half * 16;
#pragma unroll
            for (int j = 0; j < 4; j++) {
                *(uint4*)(Bh + sb + 4 * j) = *(const uint4*)(gW0h + gb + 4 * j);
                *(uint4*)(Bl + sb + 4 * j) = *(const uint4*)(gW0l + gb + 4 * j);
            }
        }
        __syncthreads();

#pragma unroll
        for (int ks = 0; ks < 4; ks++) {
            int kb = ks * 8;
            unsigned ah[2][4], al[2][4];
#pragma unroll
            for (int mt = 0; mt < 2; mt++) {
                int base = (wm * 32 + mt * 16 + gid) * ASTR + kb + tg;
                ah[mt][0] = Ah[base];
                ah[mt][1] = Ah[base + 8 * ASTR];
                ah[mt][2] = Ah[base + 4];
                ah[mt][3] = Ah[base + 8 * ASTR + 4];
                al[mt][0] = Al[base];
                al[mt][1] = Al[base + 8 * ASTR];
                al[mt][2] = Al[base + 4];
                al[mt][3] = Al[base + 8 * ASTR + 4];
            }
#pragma unroll
            for (int nt = 0; nt < 8; nt++) {
                int nb = (wn * 64 + nt * 8 + gid) * ASTR + kb + tg;
                unsigned bh0 = Bh[nb], bh1 = Bh[nb + 4];
                unsigned bl0 = Bl[nb], bl1 = Bl[nb + 4];
#pragma unroll
                for (int mt = 0; mt < 2; mt++) {
                    mma_bf16(acc[mt][nt], ah[mt], bh0, bh1);
                    mma_bf16(acc[mt][nt], ah[mt], bl0, bl1);
                    mma_bf16(acc[mt][nt], al[mt], bh0, bh1);
                }
            }
        }
        __syncthreads();
    }

#pragma unroll
    for (int mt = 0; mt < 2; mt++)
#pragma unroll
        for (int h = 0; h < 2; h++) {
            int row = rb + wm * 32 + mt * 16 + h * 8 + gid;
            if (row < n) {
#pragma unroll
                for (int nt = 0; nt < 8; nt++) {
                    int col = wn * 64 + nt * 8 + tg * 2;
                    float b0 = __ldg(bias + col), b1 = __ldg(bias + col + 1);
                    float2 v = make_float2(acc[mt][nt][2 * h] + b0,
                                           acc[mt][nt][2 * h + 1] + b1);
                    *(float2*)(out + (size_t)row * DDIM + col) = v;
                }
            }
        }
}

// ---------------------------------------------------------------------------
// Fused kernel 1: gemm0 tiles and ELL-fill chunks interleaved in one grid.
// ---------------------------------------------------------------------------
__global__ void __launch_bounds__(256, 2)
fused0_kernel(const float* __restrict__ x, const float* __restrict__ b_gc,
              const int* __restrict__ src, const int* __restrict__ dst,
              const float* __restrict__ vals,
              int n, int e, int gblocks, int fillchunks) {
    extern __shared__ unsigned smu[];
    int b  = blockIdx.x;
    int g3 = b / 3, r = b % 3;
    if (r == 0) {
        if (g3 < gblocks)
            gemm0_tile(x, b_gc, g_support, n, g3, smu);
        return;
    }
    int fb = g3 * 2 + (r - 1);
    if (fb >= fillchunks) return;
    int base = fb * 1024 + threadIdx.x * 4;
#pragma unroll
    for (int j = 0; j < 4; j++) {
        int i = base + j;
        if (i >= e) break;
        int d = __ldg(dst + i);
        int s = __ldg(src + i);
        float v = __ldg(vals + i);
        int slot = atomicAdd(&g_deg[d], 1);
        if (slot < CAP) {
            g_ell[(size_t)d * CAP + slot] = make_uint2((unsigned)s, __float_as_uint(v));
        } else {
            int o = atomicAdd(&g_ovf_cnt, 1);
            if (o < OVFMAX)
                g_ovf[o] = make_uint4((unsigned)s, (unsigned)d, __float_as_uint(v), 0u);
        }
    }
}

// ---------------------------------------------------------------------------
// Fused kernel 2: gather (8-edge-deep, saturates L2 at 16 warps/SM) + ReLU +
// bf16-split straight into full-K A smem + GEMM(W2^T) + rownorm epilogue.
// agg never exists in global memory.
// ---------------------------------------------------------------------------
__global__ void __launch_bounds__(256, 2)
fusedg1_kernel(const float* __restrict__ b2, float* __restrict__ out, int n) {
    extern __shared__ unsigned smu[];
    unsigned* Ah = smu;                      // [128][68]
    unsigned* Al = smu + 128 * AFSTR;
    unsigned* Bh = smu + 2 * 128 * AFSTR;    // [128][36]
    unsigned* Bl = Bh + 128 * ASTR;

    const int tid  = threadIdx.x;
    const int lane = tid & 31;
    const int wid  = tid >> 5;
    const int gid  = lane >> 2;
    const int tg   = lane & 3;
    const int wm   = wid >> 1;
    const int wn   = wid & 1;
    const int rb   = blockIdx.x * 128;

    // ---- phase 1: gather 16 rows per warp, 8 edges in flight per iter ----
    for (int t = 0; t < 16; t++) {
        int row  = wid * 16 + t;
        int node = rb + row;
        float4 acc = make_float4(0.f, 0.f, 0.f, 0.f);
        if (node < n) {
            int raw = __ldg(&g_deg[node]);
            int cnt = min(raw, CAP);
            const uint4* el4 = (const uint4*)(g_ell + (size_t)node * CAP);
            int nb8 = cnt >> 3;
            for (int q = 0; q < nb8; q++) {
                const uint4* p = el4 + 4 * q;
                uint4 m0 = __ldg(p),     m1 = __ldg(p + 1);
                uint4 m2 = __ldg(p + 2), m3 = __ldg(p + 3);
                float4 s0 = ((const float4*)(g_support + (size_t)m0.x * DDIM))[lane];
                float4 s1 = ((const float4*)(g_support + (size_t)m0.z * DDIM))[lane];
                float4 s2 = ((const float4*)(g_support + (size_t)m1.x * DDIM))[lane];
                float4 s3 = ((const float4*)(g_support + (size_t)m1.z * DDIM))[lane];
                float4 s4 = ((const float4*)(g_support + (size_t)m2.x * DDIM))[lane];
                float4 s5 = ((const float4*)(g_support + (size_t)m2.z * DDIM))[lane];
                float4 s6 = ((const float4*)(g_support + (size_t)m3.x * DDIM))[lane];
                float4 s7 = ((const float4*)(g_support + (size_t)m3.z * DDIM))[lane];
                fma4(acc, s0, __uint_as_float(m0.y));
                fma4(acc, s1, __uint_as_float(m0.w));
                fma4(acc, s2, __uint_as_float(m1.y));
                fma4(acc, s3, __uint_as_float(m1.w));
                fma4(acc, s4, __uint_as_float(m2.y));
                fma4(acc, s5, __uint_as_float(m2.w));
                fma4(acc, s6, __uint_as_float(m3.y));
                fma4(acc, s7, __uint_as_float(m3.w));
            }
            int i = nb8 * 8;
            if (i + 3 < cnt) {                    // 4-deep remainder block
                const uint4* p = el4 + (i >> 1);
                uint4 m0 = __ldg(p), m1 = __ldg(p + 1);
                float4 s0 = ((const float4*)(g_support + (size_t)m0.x * DDIM))[lane];
                float4 s1 = ((const float4*)(g_support + (size_t)m0.z * DDIM))[lane];
                float4 s2 = ((const float4*)(g_support + (size_t)m1.x * DDIM))[lane];
                float4 s3 = ((const float4*)(g_support + (size_t)m1.z * DDIM))[lane];
                fma4(acc, s0, __uint_as_float(m0.y));
                fma4(acc, s1, __uint_as_float(m0.w));
                fma4(acc, s2, __uint_as_float(m1.y));
                fma4(acc, s3, __uint_as_float(m1.w));
                i += 4;
            }
            for (; i < cnt; i++) {
                uint2 m = __ldg(g_ell + (size_t)node * CAP + i);
                float4 s = ((const float4*)(g_support + (size_t)m.x * DDIM))[lane];
                fma4(acc, s, __uint_as_float(m.y));
            }
            if (raw > CAP) {        // ~never
                int c = min(g_ovf_cnt, OVFMAX);
                for (int j = 0; j < c; j++) {
                    uint4 m = g_ovf[j];
                    if (m.y == (unsigned)node) {
                        float4 s = ((const float4*)(g_support + (size_t)m.x * DDIM))[lane];
                        fma4(acc, s, __uint_as_float(m.z));
                    }
                }
            }
        }
        // ReLU + bf16 split; lane covers k dims [4*lane, 4*lane+4)
        acc.x = fmaxf(acc.x, 0.f); acc.y = fmaxf(acc.y, 0.f);
        acc.z = fmaxf(acc.z, 0.f); acc.w = fmaxf(acc.w, 0.f);
        unsigned h0, l0, h1, l1;
        split_pair(acc.x, acc.y, h0, l0);
        split_pair(acc.z, acc.w, h1, l1);
        int sa = row * AFSTR + lane * 2;
        *(uint2*)(Ah + sa) = make_uint2(h0, h1);
        *(uint2*)(Al + sa) = make_uint2(l0, l1);
    }
    __syncthreads();

    // ---- phase 2: GEMM with W2^T ----
    float acc[2][8][4];
#pragma unroll
    for (int mt = 0; mt < 2; mt++)
#pragma unroll
        for (int nt = 0; nt < 8; nt++)
#pragma unroll
            for (int j = 0; j < 4; j++) acc[mt][nt][j] = 0.f;

#pragma unroll
    for (int kc0 = 0; kc0 < DDIM; kc0 += KC) {
        {
            int nn   = tid >> 1;
            int half = tid & 1;
            int gb = nn * (DDIM / 2) + (kc0 >> 1) + half * 16;
            int sb = nn * ASTR + half * 16;
#pragma unroll
            for (int j = 0; j < 4; j++) {
                *(uint4*)(Bh + sb + 4 * j) = *(const uint4*)(gW1h + gb + 4 * j);
                *(uint4*)(Bl + sb + 4 * j) = *(const uint4*)(gW1l + gb + 4 * j);
            }
        }
        __syncthreads();

#pragma unroll
        for (int ks = 0; ks < 4; ks++) {
            int kb = ks * 8;
            int ka = (kc0 >> 1) + kb;       // A is full-K
            unsigned ah[2][4], al[2][4];
#pragma unroll
            for (int mt = 0; mt < 2; mt++) {
                int base = (wm * 32 + mt * 16 + gid) * AFSTR + ka + tg;
                ah[mt][0] = Ah[base];
                ah[mt][1] = Ah[base + 8 * AFSTR];
                ah[mt][2] = Ah[base + 4];
                ah[mt][3] = Ah[base + 8 * AFSTR + 4];
                al[mt][0] = Al[base];
                al[mt][1] = Al[base + 8 * AFSTR];
                al[mt][2] = Al[base + 4];
                al[mt][3] = Al[base + 8 * AFSTR + 4];
            }
#pragma unroll
            for (int nt = 0; nt < 8; nt++) {
                int nb = (wn * 64 + nt * 8 + gid) * ASTR + kb + tg;
                unsigned bh0 = Bh[nb], bh1 = Bh[nb + 4];
                unsigned bl0 = Bl[nb], bl1 = Bl[nb + 4];
#pragma unroll
                for (int mt = 0; mt < 2; mt++) {
                    mma_bf16(acc[mt][nt], ah[mt], bh0, bh1);
                    mma_bf16(acc[mt][nt], ah[mt], bl0, bl1);
                    mma_bf16(acc[mt][nt], al[mt], bh0, bh1);
                }
            }
        }
        __syncthreads();
    }

    // ---- epilogue: bias + rownorm ----
    float* red = (float*)Bh;     // safe: sync above, Bh no longer read
#pragma unroll
    for (int mt = 0; mt < 2; mt++)
#pragma unroll
        for (int nt = 0; nt < 8; nt++) {
            int col = wn * 64 + nt * 8 + tg * 2;
            float b0 = __ldg(b2 + col), b1 = __ldg(b2 + col + 1);
            acc[mt][nt][0] += b0; acc[mt][nt][1] += b1;
            acc[mt][nt][2] += b0; acc[mt][nt][3] += b1;
        }
#pragma unroll
    for (int mt = 0; mt < 2; mt++)
#pragma unroll
        for (int h = 0; h < 2; h++) {
            float ss = 0.f;
#pragma unroll
            for (int nt = 0; nt < 8; nt++) {
                ss = fmaf(acc[mt][nt][2 * h], acc[mt][nt][2 * h], ss);
                ss = fmaf(acc[mt][nt][2 * h + 1], acc[mt][nt][2 * h + 1], ss);
            }
            ss += __shfl_xor_sync(0xffffffffu, ss, 1);
            ss += __shfl_xor_sync(0xffffffffu, ss, 2);
            if (tg == 0)
                red[(wm * 32 + mt * 16 + h * 8 + gid) * 2 + wn] = ss;
        }
    __syncthreads();
#pragma unroll
    for (int mt = 0; mt < 2; mt++)
#pragma unroll
        for (int h = 0; h < 2; h++) {
            int rl  = wm * 32 + mt * 16 + h * 8 + gid;
            int row = rb + rl;
            float inv = 1.f / sqrtf(red[rl * 2] + red[rl * 2 + 1]);
            if (row < n) {
#pragma unroll
                for (int nt = 0; nt < 8; nt++) {
                    int col = wn * 64 + nt * 8 + tg * 2;
                    float2 v = make_float2(acc[mt][nt][2 * h] * inv,
                                           acc[mt][nt][2 * h + 1] * inv);
                    *(float2*)(out + (size_t)row * DDIM + col) = v;
                }
            }
        }
}

// ---------------------------------------------------------------------------
extern "C" void kernel_launch(void* const* d_in, const int* in_sizes, int n_in,
                              void* d_out, int out_size) {
    const float* x    = (const float*)d_in[0];
    const float* vals = (const float*)d_in[1];
    const float* W_gc = (const float*)d_in[2];
    const float* b_gc = (const float*)d_in[3];
    const float* W2   = (const float*)d_in[4];
    const float* b2   = (const float*)d_in[5];
    const int*   src  = (const int*)d_in[6];
    const int*   dst  = (const int*)d_in[7];

    const int n = in_sizes[0] / DDIM;
    const int e = in_sizes[1];

    const int smem0 = 4 * 128 * ASTR * 4;                       // 73728 B
    const int smem1 = (2 * 128 * AFSTR + 2 * 128 * ASTR) * 4;   // 106496 B
    cudaFuncSetAttribute(fused0_kernel,
                         cudaFuncAttributeMaxDynamicSharedMemorySize, smem0);
    cudaFuncSetAttribute(fusedg1_kernel,
                         cudaFuncAttributeMaxDynamicSharedMemorySize, smem1);

    // 1) init: zero deg/ovf + pre-split weights
    int ithreads = n > 2 * DDIM * (DDIM / 2) ? n : 2 * DDIM * (DDIM / 2);
    init_kernel<<<(ithreads + 255) / 256, 256>>>(n, W_gc, W2);

    // 2) fused: gemm0 (support = x@W_gc + b_gc) || ELL fill
    int gblocks = (n + 127) / 128;
    int fillchunks = (e + 1023) / 1024;
    int gb2 = gblocks > (fillchunks + 1) / 2 ? gblocks : (fillchunks + 1) / 2;
    fused0_kernel<<<3 * gb2, 256, smem0>>>(x, b_gc, src, dst, vals,
                                           n, e, gblocks, fillchunks);

    // 3) fused gather(8-deep) + gemm1 + rownorm (agg never hits global memory)
    fusedg1_kernel<<<gblocks, 256, smem1>>>(b2, (float*)d_out, n);
}

// round 11
// speedup vs baseline: 1.4660x; 1.2151x over previous
#include <cuda_runtime.h>
#include <cuda_bf16.h>
#include <math.h>

#define DDIM 128
#define NMAX 50000
#define EMAX 800000
#define ASTR 36            // bf16x2 stride per row (32 data + 4 pad), %32==4 -> conflict-free
#define KC   64            // k-chunk (32 bf16x2)
#define CAP  64            // ELL capacity per node (Poisson(16): max deg ~45)
#define OVFMAX 65536
#define K2   (DDIM / 2)    // 64 bf16x2 per row

// Scratch (alloc-free rule: __device__ globals)
__device__ float    g_support[(size_t)NMAX * DDIM];
__device__ unsigned g_aggh[(size_t)NMAX * K2];   // relu(agg) bf16x2 hi
__device__ unsigned g_aggl[(size_t)NMAX * K2];   // relu(agg) bf16x2 lo
__device__ int      g_deg[NMAX];
__device__ uint2    g_ell[(size_t)NMAX * CAP];   // (src, val_bits) per slot
__device__ int      g_ovf_cnt;
__device__ uint4    g_ovf[OVFMAX];               // (src, dst, val_bits, -)
// pre-split weights, bf16x2 hi/lo, layout [n][k2]
__device__ unsigned gW0h[DDIM * K2], gW0l[DDIM * K2];
__device__ unsigned gW1h[DDIM * K2], gW1l[DDIM * K2];

// ---------------------------------------------------------------------------
__device__ __forceinline__ void split_pair(float x, float y, unsigned& hp, unsigned& lp) {
    __nv_bfloat16 hx = __float2bfloat16_rn(x);
    __nv_bfloat16 hy = __float2bfloat16_rn(y);
    __nv_bfloat16 lx = __float2bfloat16_rn(x - __bfloat162float(hx));
    __nv_bfloat16 ly = __float2bfloat16_rn(y - __bfloat162float(hy));
    hp = (unsigned)__bfloat16_as_ushort(hx) | ((unsigned)__bfloat16_as_ushort(hy) << 16);
    lp = (unsigned)__bfloat16_as_ushort(lx) | ((unsigned)__bfloat16_as_ushort(ly) << 16);
}

__device__ __forceinline__ void mma_bf16(float c[4], const unsigned a[4],
                                         unsigned b0, unsigned b1) {
    asm volatile(
        "mma.sync.aligned.m16n8k16.row.col.f32.bf16.bf16.f32 "
        "{%0,%1,%2,%3}, {%4,%5,%6,%7}, {%8,%9}, {%0,%1,%2,%3};"
        : "+f"(c[0]), "+f"(c[1]), "+f"(c[2]), "+f"(c[3])
        : "r"(a[0]), "r"(a[1]), "r"(a[2]), "r"(a[3]), "r"(b0), "r"(b1));
}

__device__ __forceinline__ void fma4(float4& a, float4 s, float v) {
    a.x = fmaf(s.x, v, a.x); a.y = fmaf(s.y, v, a.y);
    a.z = fmaf(s.z, v, a.z); a.w = fmaf(s.w, v, a.w);
}

// ---------------------------------------------------------------------------
// Init: zero deg + ovf counter, pre-split both weight matrices.
// ---------------------------------------------------------------------------
__global__ void init_kernel(int n, const float* __restrict__ W_gc,
                            const float* __restrict__ W2) {
    int i = blockIdx.x * blockDim.x + threadIdx.x;
    if (i < n) g_deg[i] = 0;
    if (i == 0) g_ovf_cnt = 0;
    if (i < DDIM * K2) {                         // W_gc: [k][n] -> [n][k2]
        int nn = i & (DDIM - 1), k2 = i >> 7;
        float w0 = __ldg(W_gc + (size_t)(2 * k2) * DDIM + nn);
        float w1 = __ldg(W_gc + (size_t)(2 * k2 + 1) * DDIM + nn);
        unsigned hp, lp;
        split_pair(w0, w1, hp, lp);
        gW0h[nn * K2 + k2] = hp;
        gW0l[nn * K2 + k2] = lp;
    } else if (i < 2 * DDIM * K2) {              // W2: [n][k] -> [n][k2]
        int j = i - DDIM * K2;
        int nn = j >> 6, k2 = j & 63;
        float w0 = __ldg(W2 + (size_t)nn * DDIM + 2 * k2);
        float w1 = __ldg(W2 + (size_t)nn * DDIM + 2 * k2 + 1);
        unsigned hp, lp;
        split_pair(w0, w1, hp, lp);
        gW1h[nn * K2 + k2] = hp;
        gW1l[nn * K2 + k2] = lp;
    }
}

// ---------------------------------------------------------------------------
// GEMM0 tile body (support = X @ W_gc + b). A split in-kernel from fp32 x.
// ---------------------------------------------------------------------------
__device__ __forceinline__ void gemm0_tile(const float* __restrict__ X,
                                           const float* __restrict__ bias,
                                           float* __restrict__ out,
                                           int n, int tileIdx, unsigned* smu) {
    unsigned* Ah = smu;
    unsigned* Al = smu + 128 * ASTR;
    unsigned* Bh = smu + 2 * 128 * ASTR;
    unsigned* Bl = smu + 3 * 128 * ASTR;

    const int tid  = threadIdx.x;
    const int lane = tid & 31;
    const int wid  = tid >> 5;
    const int gid  = lane >> 2;
    const int tg   = lane & 3;
    const int wm   = wid >> 1;
    const int wn   = wid & 1;
    const int rb   = tileIdx * 128;

    float acc[2][8][4];
#pragma unroll
    for (int mt = 0; mt < 2; mt++)
#pragma unroll
        for (int nt = 0; nt < 8; nt++)
#pragma unroll
            for (int j = 0; j < 4; j++) acc[mt][nt][j] = 0.f;

#pragma unroll
    for (int kc0 = 0; kc0 < DDIM; kc0 += KC) {
        {
            int rl = tid >> 4;
            int c4 = (tid & 15) * 4;
#pragma unroll
            for (int i = 0; i < 8; i++) {
                int row  = rl + 16 * i;
                int grow = rb + row;
                float4 v = make_float4(0.f, 0.f, 0.f, 0.f);
                if (grow < n)
                    v = *(const float4*)(X + (size_t)grow * DDIM + kc0 + c4);
                unsigned h0, l0, h1, l1;
                split_pair(v.x, v.y, h0, l0);
                split_pair(v.z, v.w, h1, l1);
                int sa = row * ASTR + (c4 >> 1);
                *(uint2*)(Ah + sa) = make_uint2(h0, h1);
                *(uint2*)(Al + sa) = make_uint2(l0, l1);
            }
        }
        {
            int nn   = tid >> 1;
            int half = tid & 1;
            int gb = nn * K2 + (kc0 >> 1) + half * 16;
            int sb = nn * ASTR + half * 16;
#pragma unroll
            for (int j = 0; j < 4; j++) {
                *(uint4*)(Bh + sb + 4 * j) = *(const uint4*)(gW0h + gb + 4 * j);
                *(uint4*)(Bl + sb + 4 * j) = *(const uint4*)(gW0l + gb + 4 * j);
            }
        }
        __syncthreads();

#pragma unroll
        for (int ks = 0; ks < 4; ks++) {
            int kb = ks * 8;
            unsigned ah[2][4], al[2][4];
#pragma unroll
            for (int mt = 0; mt < 2; mt++) {
                int base = (wm * 32 + mt * 16 + gid) * ASTR + kb + tg;
                ah[mt][0] = Ah[base];
                ah[mt][1] = Ah[base + 8 * ASTR];
                ah[mt][2] = Ah[base + 4];
                ah[mt][3] = Ah[base + 8 * ASTR + 4];
                al[mt][0] = Al[base];
                al[mt][1] = Al[base + 8 * ASTR];
                al[mt][2] = Al[base + 4];
                al[mt][3] = Al[base + 8 * ASTR + 4];
            }
#pragma unroll
            for (int nt = 0; nt < 8; nt++) {
                int nb = (wn * 64 + nt * 8 + gid) * ASTR + kb + tg;
                unsigned bh0 = Bh[nb], bh1 = Bh[nb + 4];
                unsigned bl0 = Bl[nb], bl1 = Bl[nb + 4];
#pragma unroll
                for (int mt = 0; mt < 2; mt++) {
                    mma_bf16(acc[mt][nt], ah[mt], bh0, bh1);
                    mma_bf16(acc[mt][nt], ah[mt], bl0, bl1);
                    mma_bf16(acc[mt][nt], al[mt], bh0, bh1);
                }
            }
        }
        __syncthreads();
    }

#pragma unroll
    for (int mt = 0; mt < 2; mt++)
#pragma unroll
        for (int h = 0; h < 2; h++) {
            int row = rb + wm * 32 + mt * 16 + h * 8 + gid;
            if (row < n) {
#pragma unroll
                for (int nt = 0; nt < 8; nt++) {
                    int col = wn * 64 + nt * 8 + tg * 2;
                    float b0 = __ldg(bias + col), b1 = __ldg(bias + col + 1);
                    float2 v = make_float2(acc[mt][nt][2 * h] + b0,
                                           acc[mt][nt][2 * h + 1] + b1);
                    *(float2*)(out + (size_t)row * DDIM + col) = v;
                }
            }
        }
}

// ---------------------------------------------------------------------------
// Fused kernel 1: gemm0 tiles and ELL-fill chunks interleaved in one grid.
// ---------------------------------------------------------------------------
__global__ void __launch_bounds__(256, 2)
fused0_kernel(const float* __restrict__ x, const float* __restrict__ b_gc,
              const int* __restrict__ src, const int* __restrict__ dst,
              const float* __restrict__ vals,
              int n, int e, int gblocks, int fillchunks) {
    extern __shared__ unsigned smu[];
    int b  = blockIdx.x;
    int g3 = b / 3, r = b % 3;
    if (r == 0) {
        if (g3 < gblocks)
            gemm0_tile(x, b_gc, g_support, n, g3, smu);
        return;
    }
    int fb = g3 * 2 + (r - 1);
    if (fb >= fillchunks) return;
    int base = fb * 1024 + threadIdx.x * 4;
#pragma unroll
    for (int j = 0; j < 4; j++) {
        int i = base + j;
        if (i >= e) break;
        int d = __ldg(dst + i);
        int s = __ldg(src + i);
        float v = __ldg(vals + i);
        int slot = atomicAdd(&g_deg[d], 1);
        if (slot < CAP) {
            g_ell[(size_t)d * CAP + slot] = make_uint2((unsigned)s, __float_as_uint(v));
        } else {
            int o = atomicAdd(&g_ovf_cnt, 1);
            if (o < OVFMAX)
                g_ovf[o] = make_uint4((unsigned)s, (unsigned)d, __float_as_uint(v), 0u);
        }
    }
}

// ---------------------------------------------------------------------------
// Standalone gather: one warp per node, 8 edges in flight per iteration
// (full occupancy, no smem). Emits ReLU'd result pre-split as bf16x2 hi/lo.
// ---------------------------------------------------------------------------
__global__ void __launch_bounds__(256)
gather_kernel(int n) {
    int g = blockIdx.x * blockDim.x + threadIdx.x;
    int node = g >> 5;
    int lane = g & 31;
    if (node >= n) return;

    int raw = __ldg(&g_deg[node]);
    int cnt = min(raw, CAP);
    const uint4* el4 = (const uint4*)(g_ell + (size_t)node * CAP);

    float4 acc = make_float4(0.f, 0.f, 0.f, 0.f);
    int nb8 = cnt >> 3;

    for (int q = 0; q < nb8; q++) {
        const uint4* p = el4 + 4 * q;
        uint4 m0 = __ldg(p),     m1 = __ldg(p + 1);
        uint4 m2 = __ldg(p + 2), m3 = __ldg(p + 3);
        float4 s0 = ((const float4*)(g_support + (size_t)m0.x * DDIM))[lane];
        float4 s1 = ((const float4*)(g_support + (size_t)m0.z * DDIM))[lane];
        float4 s2 = ((const float4*)(g_support + (size_t)m1.x * DDIM))[lane];
        float4 s3 = ((const float4*)(g_support + (size_t)m1.z * DDIM))[lane];
        float4 s4 = ((const float4*)(g_support + (size_t)m2.x * DDIM))[lane];
        float4 s5 = ((const float4*)(g_support + (size_t)m2.z * DDIM))[lane];
        float4 s6 = ((const float4*)(g_support + (size_t)m3.x * DDIM))[lane];
        float4 s7 = ((const float4*)(g_support + (size_t)m3.z * DDIM))[lane];
        fma4(acc, s0, __uint_as_float(m0.y));
        fma4(acc, s1, __uint_as_float(m0.w));
        fma4(acc, s2, __uint_as_float(m1.y));
        fma4(acc, s3, __uint_as_float(m1.w));
        fma4(acc, s4, __uint_as_float(m2.y));
        fma4(acc, s5, __uint_as_float(m2.w));
        fma4(acc, s6, __uint_as_float(m3.y));
        fma4(acc, s7, __uint_as_float(m3.w));
    }
    int i = nb8 * 8;
    if (i + 3 < cnt) {                    // 4-deep remainder block
        const uint4* p = el4 + (i >> 1);
        uint4 m0 = __ldg(p), m1 = __ldg(p + 1);
        float4 s0 = ((const float4*)(g_support + (size_t)m0.x * DDIM))[lane];
        float4 s1 = ((const float4*)(g_support + (size_t)m0.z * DDIM))[lane];
        float4 s2 = ((const float4*)(g_support + (size_t)m1.x * DDIM))[lane];
        float4 s3 = ((const float4*)(g_support + (size_t)m1.z * DDIM))[lane];
        fma4(acc, s0, __uint_as_float(m0.y));
        fma4(acc, s1, __uint_as_float(m0.w));
        fma4(acc, s2, __uint_as_float(m1.y));
        fma4(acc, s3, __uint_as_float(m1.w));
        i += 4;
    }
    for (; i < cnt; i++) {
        uint2 m = __ldg(g_ell + (size_t)node * CAP + i);
        float4 s = ((const float4*)(g_support + (size_t)m.x * DDIM))[lane];
        fma4(acc, s, __uint_as_float(m.y));
    }
    if (raw > CAP) {        // ~never: pick up this node's overflow edges
        int c = min(g_ovf_cnt, OVFMAX);
        for (int j = 0; j < c; j++) {
            uint4 m = g_ovf[j];
            if (m.y == (unsigned)node) {
                float4 s = ((const float4*)(g_support + (size_t)m.x * DDIM))[lane];
                fma4(acc, s, __uint_as_float(m.z));
            }
        }
    }

    // ReLU + bf16 split; lane covers k dims [4*lane, 4*lane+4) -> k2 = 2*lane(+1)
    acc.x = fmaxf(acc.x, 0.f); acc.y = fmaxf(acc.y, 0.f);
    acc.z = fmaxf(acc.z, 0.f); acc.w = fmaxf(acc.w, 0.f);
    unsigned h0, l0, h1, l1;
    split_pair(acc.x, acc.y, h0, l0);
    split_pair(acc.z, acc.w, h1, l1);
    size_t sa = (size_t)node * K2 + lane * 2;
    *(uint2*)(g_aggh + sa) = make_uint2(h0, h1);
    *(uint2*)(g_aggl + sa) = make_uint2(l0, l1);
}

// ---------------------------------------------------------------------------
// GEMM1: out = rownorm(relu(agg) @ W2^T + b2). A comes pre-split from gather
// (straight uint2 copies, no conversion work in the staging path).
// ---------------------------------------------------------------------------
__global__ void __launch_bounds__(256, 2)
gemm1_kernel(const float* __restrict__ b2, float* __restrict__ out, int n) {
    extern __shared__ unsigned smu[];
    unsigned* Ah = smu;
    unsigned* Al = smu + 128 * ASTR;
    unsigned* Bh = smu + 2 * 128 * ASTR;
    unsigned* Bl = smu + 3 * 128 * ASTR;

    const int tid  = threadIdx.x;
    const int lane = tid & 31;
    const int wid  = tid >> 5;
    const int gid  = lane >> 2;
    const int tg   = lane & 3;
    const int wm   = wid >> 1;
    const int wn   = wid & 1;
    const int rb   = blockIdx.x * 128;

    float acc[2][8][4];
#pragma unroll
    for (int mt = 0; mt < 2; mt++)
#pragma unroll
        for (int nt = 0; nt < 8; nt++)
#pragma unroll
            for (int j = 0; j < 4; j++) acc[mt][nt][j] = 0.f;

#pragma unroll
    for (int kc0 = 0; kc0 < DDIM; kc0 += KC) {
        // ---- stage A: straight uint2 copies of pre-split agg ----
        {
            int rl = tid >> 4;            // 0..15
            int c2 = (tid & 15) * 2;      // k2 offset 0..30
#pragma unroll
            for (int i = 0; i < 8; i++) {
                int row  = rl + 16 * i;
                int grow = rb + row;
                uint2 h = make_uint2(0u, 0u), l = make_uint2(0u, 0u);
                if (grow < n) {
                    size_t ga = (size_t)grow * K2 + (kc0 >> 1) + c2;
                    h = *(const uint2*)(g_aggh + ga);
                    l = *(const uint2*)(g_aggl + ga);
                }
                int sa = row * ASTR + (kc0 ? c2 : c2);   // per-chunk layout
                *(uint2*)(Ah + sa) = h;
                *(uint2*)(Al + sa) = l;
            }
        }
        // ---- stage B ----
        {
            int nn   = tid >> 1;
            int half = tid & 1;
            int gb = nn * K2 + (kc0 >> 1) + half * 16;
            int sb = nn * ASTR + half * 16;
#pragma unroll
            for (int j = 0; j < 4; j++) {
                *(uint4*)(Bh + sb + 4 * j) = *(const uint4*)(gW1h + gb + 4 * j);
                *(uint4*)(Bl + sb + 4 * j) = *(const uint4*)(gW1l + gb + 4 * j);
            }
        }
        __syncthreads();

#pragma unroll
        for (int ks = 0; ks < 4; ks++) {
            int kb = ks * 8;
            unsigned ah[2][4], al[2][4];
#pragma unroll
            for (int mt = 0; mt < 2; mt++) {
                int base = (wm * 32 + mt * 16 + gid) * ASTR + kb + tg;
                ah[mt][0] = Ah[base];
                ah[mt][1] = Ah[base + 8 * ASTR];
                ah[mt][2] = Ah[base + 4];
                ah[mt][3] = Ah[base + 8 * ASTR + 4];
                al[mt][0] = Al[base];
                al[mt][1] = Al[base + 8 * ASTR];
                al[mt][2] = Al[base + 4];
                al[mt][3] = Al[base + 8 * ASTR + 4];
            }
#pragma unroll
            for (int nt = 0; nt < 8; nt++) {
                int nb = (wn * 64 + nt * 8 + gid) * ASTR + kb + tg;
                unsigned bh0 = Bh[nb], bh1 = Bh[nb + 4];
                unsigned bl0 = Bl[nb], bl1 = Bl[nb + 4];
#pragma unroll
                for (int mt = 0; mt < 2; mt++) {
                    mma_bf16(acc[mt][nt], ah[mt], bh0, bh1);
                    mma_bf16(acc[mt][nt], ah[mt], bl0, bl1);
                    mma_bf16(acc[mt][nt], al[mt], bh0, bh1);
                }
            }
        }
        __syncthreads();
    }

    // ---- epilogue: bias + rownorm ----
    float* red = (float*)smu;
#pragma unroll
    for (int mt = 0; mt < 2; mt++)
#pragma unroll
        for (int nt = 0; nt < 8; nt++) {
            int col = wn * 64 + nt * 8 + tg * 2;
            float b0 = __ldg(b2 + col), b1 = __ldg(b2 + col + 1);
            acc[mt][nt][0] += b0; acc[mt][nt][1] += b1;
            acc[mt][nt][2] += b0; acc[mt][nt][3] += b1;
        }
#pragma unroll
    for (int mt = 0; mt < 2; mt++)
#pragma unroll
        for (int h = 0; h < 2; h++) {
            float ss = 0.f;
#pragma unroll
            for (int nt = 0; nt < 8; nt++) {
                ss = fmaf(acc[mt][nt][2 * h], acc[mt][nt][2 * h], ss);
                ss = fmaf(acc[mt][nt][2 * h + 1], acc[mt][nt][2 * h + 1], ss);
            }
            ss += __shfl_xor_sync(0xffffffffu, ss, 1);
            ss += __shfl_xor_sync(0xffffffffu, ss, 2);
            if (tg == 0)
                red[(wm * 32 + mt * 16 + h * 8 + gid) * 2 + wn] = ss;
        }
    __syncthreads();
#pragma unroll
    for (int mt = 0; mt < 2; mt++)
#pragma unroll
        for (int h = 0; h < 2; h++) {
            int rl  = wm * 32 + mt * 16 + h * 8 + gid;
            int row = rb + rl;
            float inv = 1.f / sqrtf(red[rl * 2] + red[rl * 2 + 1]);
            if (row < n) {
#pragma unroll
                for (int nt = 0; nt < 8; nt++) {
                    int col = wn * 64 + nt * 8 + tg * 2;
                    float2 v = make_float2(acc[mt][nt][2 * h] * inv,
                                           acc[mt][nt][2 * h + 1] * inv);
                    *(float2*)(out + (size_t)row * DDIM + col) = v;
                }
            }
        }
}

// ---------------------------------------------------------------------------
extern "C" void kernel_launch(void* const* d_in, const int* in_sizes, int n_in,
                              void* d_out, int out_size) {
    const float* x    = (const float*)d_in[0];
    const float* vals = (const float*)d_in[1];
    const float* W_gc = (const float*)d_in[2];
    const float* b_gc = (const float*)d_in[3];
    const float* W2   = (const float*)d_in[4];
    const float* b2   = (const float*)d_in[5];
    const int*   src  = (const int*)d_in[6];
    const int*   dst  = (const int*)d_in[7];

    const int n = in_sizes[0] / DDIM;
    const int e = in_sizes[1];

    const int smem = 4 * 128 * ASTR * 4;   // 73728 B
    cudaFuncSetAttribute(fused0_kernel,
                         cudaFuncAttributeMaxDynamicSharedMemorySize, smem);
    cudaFuncSetAttribute(gemm1_kernel,
                         cudaFuncAttributeMaxDynamicSharedMemorySize, smem);

    // 1) init: zero deg/ovf + pre-split weights
    int ithreads = n > 2 * DDIM * K2 ? n : 2 * DDIM * K2;
    init_kernel<<<(ithreads + 255) / 256, 256>>>(n, W_gc, W2);

    // 2) fused: gemm0 (support = x@W_gc + b_gc) || ELL fill
    int gblocks = (n + 127) / 128;
    int fillchunks = (e + 1023) / 1024;
    int gb2 = gblocks > (fillchunks + 1) / 2 ? gblocks : (fillchunks + 1) / 2;
    fused0_kernel<<<3 * gb2, 256, smem>>>(x, b_gc, src, dst, vals,
                                          n, e, gblocks, fillchunks);

    // 3) standalone gather (8-deep MLP, full occupancy), emits bf16 hi/lo agg
    long long gthreads = (long long)n * 32;
    gather_kernel<<<(int)((gthreads + 255) / 256), 256>>>(n);

    // 4) gemm1: out = rownorm(relu(agg) @ W2^T + b2)
    gemm1_kernel<<<gblocks, 256, smem>>>(b2, (float*)d_out, n);
}

// round 12
// speedup vs baseline: 1.4927x; 1.0182x over previous
#include <cuda_runtime.h>
#include <cuda_bf16.h>
#include <math.h>

#define DDIM 128
#define NMAX 50000
#define EMAX 800000
#define ASTR 36            // bf16x2 stride per row (32 data + 4 pad), %32==4 -> conflict-free
#define KC   64            // k-chunk (32 bf16x2)
#define CAP  64            // ELL capacity per node (Poisson(16): max deg ~45)
#define OVFMAX 65536
#define K2   (DDIM / 2)    // 64 bf16x2 per row
#define K4   (DDIM / 4)    // 32 uint4 per packed agg row

// Scratch (alloc-free rule: __device__ globals)
__device__ float    g_support[(size_t)NMAX * DDIM];
// packed relu(agg): per uint4 = {hi(k2), hi(k2+1), lo(k2), lo(k2+1)}
__device__ uint4    g_agg[(size_t)NMAX * K4];
__device__ int      g_deg[NMAX];
__device__ uint2    g_ell[(size_t)NMAX * CAP];   // (src, val_bits) per slot
__device__ int      g_ovf_cnt;
__device__ uint4    g_ovf[OVFMAX];               // (src, dst, val_bits, -)
// pre-split weights, bf16x2 hi/lo, layout [n][k2]
__device__ unsigned gW0h[DDIM * K2], gW0l[DDIM * K2];
__device__ unsigned gW1h[DDIM * K2], gW1l[DDIM * K2];

// ---------------------------------------------------------------------------
__device__ __forceinline__ void split_pair(float x, float y, unsigned& hp, unsigned& lp) {
    __nv_bfloat16 hx = __float2bfloat16_rn(x);
    __nv_bfloat16 hy = __float2bfloat16_rn(y);
    __nv_bfloat16 lx = __float2bfloat16_rn(x - __bfloat162float(hx));
    __nv_bfloat16 ly = __float2bfloat16_rn(y - __bfloat162float(hy));
    hp = (unsigned)__bfloat16_as_ushort(hx) | ((unsigned)__bfloat16_as_ushort(hy) << 16);
    lp = (unsigned)__bfloat16_as_ushort(lx) | ((unsigned)__bfloat16_as_ushort(ly) << 16);
}

__device__ __forceinline__ void mma_bf16(float c[4], const unsigned a[4],
                                         unsigned b0, unsigned b1) {
    asm volatile(
        "mma.sync.aligned.m16n8k16.row.col.f32.bf16.bf16.f32 "
        "{%0,%1,%2,%3}, {%4,%5,%6,%7}, {%8,%9}, {%0,%1,%2,%3};"
        : "+f"(c[0]), "+f"(c[1]), "+f"(c[2]), "+f"(c[3])
        : "r"(a[0]), "r"(a[1]), "r"(a[2]), "r"(a[3]), "r"(b0), "r"(b1));
}

__device__ __forceinline__ void fma4(float4& a, float4 s, float v) {
    a.x = fmaf(s.x, v, a.x); a.y = fmaf(s.y, v, a.y);
    a.z = fmaf(s.z, v, a.z); a.w = fmaf(s.w, v, a.w);
}

// ---------------------------------------------------------------------------
// Init: zero deg + ovf counter, pre-split both weight matrices.
// ---------------------------------------------------------------------------
__global__ void init_kernel(int n, const float* __restrict__ W_gc,
                            const float* __restrict__ W2) {
    int i = blockIdx.x * blockDim.x + threadIdx.x;
    if (i < n) g_deg[i] = 0;
    if (i == 0) g_ovf_cnt = 0;
    if (i < DDIM * K2) {                         // W_gc: [k][n] -> [n][k2]
        int nn = i & (DDIM - 1), k2 = i >> 7;
        float w0 = __ldg(W_gc + (size_t)(2 * k2) * DDIM + nn);
        float w1 = __ldg(W_gc + (size_t)(2 * k2 + 1) * DDIM + nn);
        unsigned hp, lp;
        split_pair(w0, w1, hp, lp);
        gW0h[nn * K2 + k2] = hp;
        gW0l[nn * K2 + k2] = lp;
    } else if (i < 2 * DDIM * K2) {              // W2: [n][k] -> [n][k2]
        int j = i - DDIM * K2;
        int nn = j >> 6, k2 = j & 63;
        float w0 = __ldg(W2 + (size_t)nn * DDIM + 2 * k2);
        float w1 = __ldg(W2 + (size_t)nn * DDIM + 2 * k2 + 1);
        unsigned hp, lp;
        split_pair(w0, w1, hp, lp);
        gW1h[nn * K2 + k2] = hp;
        gW1l[nn * K2 + k2] = lp;
    }
}

// ---------------------------------------------------------------------------
// GEMM0 tile body (support = X @ W_gc + b). A split in-kernel from fp32 x.
// ---------------------------------------------------------------------------
__device__ __forceinline__ void gemm0_tile(const float* __restrict__ X,
                                           const float* __restrict__ bias,
                                           float* __restrict__ out,
                                           int n, int tileIdx, unsigned* smu) {
    unsigned* Ah = smu;
    unsigned* Al = smu + 128 * ASTR;
    unsigned* Bh = smu + 2 * 128 * ASTR;
    unsigned* Bl = smu + 3 * 128 * ASTR;

    const int tid  = threadIdx.x;
    const int lane = tid & 31;
    const int wid  = tid >> 5;
    const int gid  = lane >> 2;
    const int tg   = lane & 3;
    const int wm   = wid >> 1;
    const int wn   = wid & 1;
    const int rb   = tileIdx * 128;

    float acc[2][8][4];
#pragma unroll
    for (int mt = 0; mt < 2; mt++)
#pragma unroll
        for (int nt = 0; nt < 8; nt++)
#pragma unroll
            for (int j = 0; j < 4; j++) acc[mt][nt][j] = 0.f;

#pragma unroll
    for (int kc0 = 0; kc0 < DDIM; kc0 += KC) {
        {
            int rl = tid >> 4;
            int c4 = (tid & 15) * 4;
#pragma unroll
            for (int i = 0; i < 8; i++) {
                int row  = rl + 16 * i;
                int grow = rb + row;
                float4 v = make_float4(0.f, 0.f, 0.f, 0.f);
                if (grow < n)
                    v = *(const float4*)(X + (size_t)grow * DDIM + kc0 + c4);
                unsigned h0, l0, h1, l1;
                split_pair(v.x, v.y, h0, l0);
                split_pair(v.z, v.w, h1, l1);
                int sa = row * ASTR + (c4 >> 1);
                *(uint2*)(Ah + sa) = make_uint2(h0, h1);
                *(uint2*)(Al + sa) = make_uint2(l0, l1);
            }
        }
        {
            int nn   = tid >> 1;
            int half = tid & 1;
            int gb = nn * K2 + (kc0 >> 1) + half * 16;
            int sb = nn * ASTR + half * 16;
#pragma unroll
            for (int j = 0; j < 4; j++) {
                *(uint4*)(Bh + sb + 4 * j) = *(const uint4*)(gW0h + gb + 4 * j);
                *(uint4*)(Bl + sb + 4 * j) = *(const uint4*)(gW0l + gb + 4 * j);
            }
        }
        __syncthreads();

#pragma unroll
        for (int ks = 0; ks < 4; ks++) {
            int kb = ks * 8;
            unsigned ah[2][4], al[2][4];
#pragma unroll
            for (int mt = 0; mt < 2; mt++) {
                int base = (wm * 32 + mt * 16 + gid) * ASTR + kb + tg;
                ah[mt][0] = Ah[base];
                ah[mt][1] = Ah[base + 8 * ASTR];
                ah[mt][2] = Ah[base + 4];
                ah[mt][3] = Ah[base + 8 * ASTR + 4];
                al[mt][0] = Al[base];
                al[mt][1] = Al[base + 8 * ASTR];
                al[mt][2] = Al[base + 4];
                al[mt][3] = Al[base + 8 * ASTR + 4];
            }
#pragma unroll
            for (int nt = 0; nt < 8; nt++) {
                int nb = (wn * 64 + nt * 8 + gid) * ASTR + kb + tg;
                unsigned bh0 = Bh[nb], bh1 = Bh[nb + 4];
                unsigned bl0 = Bl[nb], bl1 = Bl[nb + 4];
#pragma unroll
                for (int mt = 0; mt < 2; mt++) {
                    mma_bf16(acc[mt][nt], ah[mt], bh0, bh1);
                    mma_bf16(acc[mt][nt], ah[mt], bl0, bl1);
                    mma_bf16(acc[mt][nt], al[mt], bh0, bh1);
                }
            }
        }
        __syncthreads();
    }

#pragma unroll
    for (int mt = 0; mt < 2; mt++)
#pragma unroll
        for (int h = 0; h < 2; h++) {
            int row = rb + wm * 32 + mt * 16 + h * 8 + gid;
            if (row < n) {
#pragma unroll
                for (int nt = 0; nt < 8; nt++) {
                    int col = wn * 64 + nt * 8 + tg * 2;
                    float b0 = __ldg(bias + col), b1 = __ldg(bias + col + 1);
                    float2 v = make_float2(acc[mt][nt][2 * h] + b0,
                                           acc[mt][nt][2 * h + 1] + b1);
                    *(float2*)(out + (size_t)row * DDIM + col) = v;
                }
            }
        }
}

// ---------------------------------------------------------------------------
// Fused kernel 1: gemm0 tiles and ELL-fill chunks interleaved in one grid.
// ---------------------------------------------------------------------------
__global__ void __launch_bounds__(256, 2)
fused0_kernel(const float* __restrict__ x, const float* __restrict__ b_gc,
              const int* __restrict__ src, const int* __restrict__ dst,
              const float* __restrict__ vals,
              int n, int e, int gblocks, int fillchunks) {
    extern __shared__ unsigned smu[];
    int b  = blockIdx.x;
    int g3 = b / 3, r = b % 3;
    if (r == 0) {
        if (g3 < gblocks)
            gemm0_tile(x, b_gc, g_support, n, g3, smu);
        return;
    }
    int fb = g3 * 2 + (r - 1);
    if (fb >= fillchunks) return;
    int base = fb * 1024 + threadIdx.x * 4;
#pragma unroll
    for (int j = 0; j < 4; j++) {
        int i = base + j;
        if (i >= e) break;
        int d = __ldg(dst + i);
        int s = __ldg(src + i);
        float v = __ldg(vals + i);
        int slot = atomicAdd(&g_deg[d], 1);
        if (slot < CAP) {
            g_ell[(size_t)d * CAP + slot] = make_uint2((unsigned)s, __float_as_uint(v));
        } else {
            int o = atomicAdd(&g_ovf_cnt, 1);
            if (o < OVFMAX)
                g_ovf[o] = make_uint4((unsigned)s, (unsigned)d, __float_as_uint(v), 0u);
        }
    }
}

// ---------------------------------------------------------------------------
// Standalone gather: one warp per node, 8 edges in flight per iteration
// (full occupancy, no smem). Emits ReLU'd result pre-split + packed:
// one uint4 {hi0, hi1, lo0, lo1} per lane (k2 = 2*lane, 2*lane+1).
// ---------------------------------------------------------------------------
__global__ void __launch_bounds__(256)
gather_kernel(int n) {
    int g = blockIdx.x * blockDim.x + threadIdx.x;
    int node = g >> 5;
    int lane = g & 31;
    if (node >= n) return;

    int raw = __ldg(&g_deg[node]);
    int cnt = min(raw, CAP);
    const uint4* el4 = (const uint4*)(g_ell + (size_t)node * CAP);

    float4 acc = make_float4(0.f, 0.f, 0.f, 0.f);
    int nb8 = cnt >> 3;

    for (int q = 0; q < nb8; q++) {
        const uint4* p = el4 + 4 * q;
        uint4 m0 = __ldg(p),     m1 = __ldg(p + 1);
        uint4 m2 = __ldg(p + 2), m3 = __ldg(p + 3);
        float4 s0 = ((const float4*)(g_support + (size_t)m0.x * DDIM))[lane];
        float4 s1 = ((const float4*)(g_support + (size_t)m0.z * DDIM))[lane];
        float4 s2 = ((const float4*)(g_support + (size_t)m1.x * DDIM))[lane];
        float4 s3 = ((const float4*)(g_support + (size_t)m1.z * DDIM))[lane];
        float4 s4 = ((const float4*)(g_support + (size_t)m2.x * DDIM))[lane];
        float4 s5 = ((const float4*)(g_support + (size_t)m2.z * DDIM))[lane];
        float4 s6 = ((const float4*)(g_support + (size_t)m3.x * DDIM))[lane];
        float4 s7 = ((const float4*)(g_support + (size_t)m3.z * DDIM))[lane];
        fma4(acc, s0, __uint_as_float(m0.y));
        fma4(acc, s1, __uint_as_float(m0.w));
        fma4(acc, s2, __uint_as_float(m1.y));
        fma4(acc, s3, __uint_as_float(m1.w));
        fma4(acc, s4, __uint_as_float(m2.y));
        fma4(acc, s5, __uint_as_float(m2.w));
        fma4(acc, s6, __uint_as_float(m3.y));
        fma4(acc, s7, __uint_as_float(m3.w));
    }
    int i = nb8 * 8;
    if (i + 3 < cnt) {                    // 4-deep remainder block
        const uint4* p = el4 + (i >> 1);
        uint4 m0 = __ldg(p), m1 = __ldg(p + 1);
        float4 s0 = ((const float4*)(g_support + (size_t)m0.x * DDIM))[lane];
        float4 s1 = ((const float4*)(g_support + (size_t)m0.z * DDIM))[lane];
        float4 s2 = ((const float4*)(g_support + (size_t)m1.x * DDIM))[lane];
        float4 s3 = ((const float4*)(g_support + (size_t)m1.z * DDIM))[lane];
        fma4(acc, s0, __uint_as_float(m0.y));
        fma4(acc, s1, __uint_as_float(m0.w));
        fma4(acc, s2, __uint_as_float(m1.y));
        fma4(acc, s3, __uint_as_float(m1.w));
        i += 4;
    }
    for (; i < cnt; i++) {
        uint2 m = __ldg(g_ell + (size_t)node * CAP + i);
        float4 s = ((const float4*)(g_support + (size_t)m.x * DDIM))[lane];
        fma4(acc, s, __uint_as_float(m.y));
    }
    if (raw > CAP) {        // ~never: pick up this node's overflow edges
        int c = min(g_ovf_cnt, OVFMAX);
        for (int j = 0; j < c; j++) {
            uint4 m = g_ovf[j];
            if (m.y == (unsigned)node) {
                float4 s = ((const float4*)(g_support + (size_t)m.x * DDIM))[lane];
                fma4(acc, s, __uint_as_float(m.z));
            }
        }
    }

    // ReLU + bf16 split; one packed uint4 store per lane
    acc.x = fmaxf(acc.x, 0.f); acc.y = fmaxf(acc.y, 0.f);
    acc.z = fmaxf(acc.z, 0.f); acc.w = fmaxf(acc.w, 0.f);
    unsigned h0, l0, h1, l1;
    split_pair(acc.x, acc.y, h0, l0);
    split_pair(acc.z, acc.w, h1, l1);
    g_agg[(size_t)node * K4 + lane] = make_uint4(h0, h1, l0, l1);
}

// ---------------------------------------------------------------------------
// GEMM1: out = rownorm(relu(agg) @ W2^T + b2). A comes pre-split + packed:
// one uint4 load -> two uint2 smem stores, zero conversion work.
// ---------------------------------------------------------------------------
__global__ void __launch_bounds__(256, 2)
gemm1_kernel(const float* __restrict__ b2, float* __restrict__ out, int n) {
    extern __shared__ unsigned smu[];
    unsigned* Ah = smu;
    unsigned* Al = smu + 128 * ASTR;
    unsigned* Bh = smu + 2 * 128 * ASTR;
    unsigned* Bl = smu + 3 * 128 * ASTR;

    const int tid  = threadIdx.x;
    const int lane = tid & 31;
    const int wid  = tid >> 5;
    const int gid  = lane >> 2;
    const int tg   = lane & 3;
    const int wm   = wid >> 1;
    const int wn   = wid & 1;
    const int rb   = blockIdx.x * 128;

    float acc[2][8][4];
#pragma unroll
    for (int mt = 0; mt < 2; mt++)
#pragma unroll
        for (int nt = 0; nt < 8; nt++)
#pragma unroll
            for (int j = 0; j < 4; j++) acc[mt][nt][j] = 0.f;

#pragma unroll
    for (int kc0 = 0; kc0 < DDIM; kc0 += KC) {
        // ---- stage A: packed uint4 loads (coalesced 256B per 16 threads) ----
        {
            int rl = tid >> 4;            // 0..15
            int q  = tid & 15;            // uint4 index within chunk (k2 = 2q)
            int qb = (kc0 >> 2) + q;      // uint4 index within row
#pragma unroll
            for (int i = 0; i < 8; i++) {
                int row  = rl + 16 * i;
                int grow = rb + row;
                uint4 u = make_uint4(0u, 0u, 0u, 0u);
                if (grow < n)
                    u = g_agg[(size_t)grow * K4 + qb];
                int sa = row * ASTR + 2 * q;
                *(uint2*)(Ah + sa) = make_uint2(u.x, u.y);
                *(uint2*)(Al + sa) = make_uint2(u.z, u.w);
            }
        }
        // ---- stage B ----
        {
            int nn   = tid >> 1;
            int half = tid & 1;
            int gb = nn * K2 + (kc0 >> 1) + half * 16;
            int sb = nn * ASTR + half * 16;
#pragma unroll
            for (int j = 0; j < 4; j++) {
                *(uint4*)(Bh + sb + 4 * j) = *(const uint4*)(gW1h + gb + 4 * j);
                *(uint4*)(Bl + sb + 4 * j) = *(const uint4*)(gW1l + gb + 4 * j);
            }
        }
        __syncthreads();

#pragma unroll
        for (int ks = 0; ks < 4; ks++) {
            int kb = ks * 8;
            unsigned ah[2][4], al[2][4];
#pragma unroll
            for (int mt = 0; mt < 2; mt++) {
                int base = (wm * 32 + mt * 16 + gid) * ASTR + kb + tg;
                ah[mt][0] = Ah[base];
                ah[mt][1] = Ah[base + 8 * ASTR];
                ah[mt][2] = Ah[base + 4];
                ah[mt][3] = Ah[base + 8 * ASTR + 4];
                al[mt][0] = Al[base];
                al[mt][1] = Al[base + 8 * ASTR];
                al[mt][2] = Al[base + 4];
                al[mt][3] = Al[base + 8 * ASTR + 4];
            }
#pragma unroll
            for (int nt = 0; nt < 8; nt++) {
                int nb = (wn * 64 + nt * 8 + gid) * ASTR + kb + tg;
                unsigned bh0 = Bh[nb], bh1 = Bh[nb + 4];
                unsigned bl0 = Bl[nb], bl1 = Bl[nb + 4];
#pragma unroll
                for (int mt = 0; mt < 2; mt++) {
                    mma_bf16(acc[mt][nt], ah[mt], bh0, bh1);
                    mma_bf16(acc[mt][nt], ah[mt], bl0, bl1);
                    mma_bf16(acc[mt][nt], al[mt], bh0, bh1);
                }
            }
        }
        __syncthreads();
    }

    // ---- epilogue: bias + rownorm ----
    float* red = (float*)smu;
#pragma unroll
    for (int mt = 0; mt < 2; mt++)
#pragma unroll
        for (int nt = 0; nt < 8; nt++) {
            int col = wn * 64 + nt * 8 + tg * 2;
            float b0 = __ldg(b2 + col), b1 = __ldg(b2 + col + 1);
            acc[mt][nt][0] += b0; acc[mt][nt][1] += b1;
            acc[mt][nt][2] += b0; acc[mt][nt][3] += b1;
        }
#pragma unroll
    for (int mt = 0; mt < 2; mt++)
#pragma unroll
        for (int h = 0; h < 2; h++) {
            float ss = 0.f;
#pragma unroll
            for (int nt = 0; nt < 8; nt++) {
                ss = fmaf(acc[mt][nt][2 * h], acc[mt][nt][2 * h], ss);
                ss = fmaf(acc[mt][nt][2 * h + 1], acc[mt][nt][2 * h + 1], ss);
            }
            ss += __shfl_xor_sync(0xffffffffu, ss, 1);
            ss += __shfl_xor_sync(0xffffffffu, ss, 2);
            if (tg == 0)
                red[(wm * 32 + mt * 16 + h * 8 + gid) * 2 + wn] = ss;
        }
    __syncthreads();
#pragma unroll
    for (int mt = 0; mt < 2; mt++)
#pragma unroll
        for (int h = 0; h < 2; h++) {
            int rl  = wm * 32 + mt * 16 + h * 8 + gid;
            int row = rb + rl;
            float inv = 1.f / sqrtf(red[rl * 2] + red[rl * 2 + 1]);
            if (row < n) {
#pragma unroll
                for (int nt = 0; nt < 8; nt++) {
                    int col = wn * 64 + nt * 8 + tg * 2;
                    float2 v = make_float2(acc[mt][nt][2 * h] * inv,
                                           acc[mt][nt][2 * h + 1] * inv);
                    *(float2*)(out + (size_t)row * DDIM + col) = v;
                }
            }
        }
}

// ---------------------------------------------------------------------------
extern "C" void kernel_launch(void* const* d_in, const int* in_sizes, int n_in,
                              void* d_out, int out_size) {
    const float* x    = (const float*)d_in[0];
    const float* vals = (const float*)d_in[1];
    const float* W_gc = (const float*)d_in[2];
    const float* b_gc = (const float*)d_in[3];
    const float* W2   = (const float*)d_in[4];
    const float* b2   = (const float*)d_in[5];
    const int*   src  = (const int*)d_in[6];
    const int*   dst  = (const int*)d_in[7];

    const int n = in_sizes[0] / DDIM;
    const int e = in_sizes[1];

    const int smem = 4 * 128 * ASTR * 4;   // 73728 B
    cudaFuncSetAttribute(fused0_kernel,
                         cudaFuncAttributeMaxDynamicSharedMemorySize, smem);
    cudaFuncSetAttribute(gemm1_kernel,
                         cudaFuncAttributeMaxDynamicSharedMemorySize, smem);

    // 1) init: zero deg/ovf + pre-split weights
    int ithreads = n > 2 * DDIM * K2 ? n : 2 * DDIM * K2;
    init_kernel<<<(ithreads + 255) / 256, 256>>>(n, W_gc, W2);

    // 2) fused: gemm0 (support = x@W_gc + b_gc) || ELL fill
    int gblocks = (n + 127) / 128;
    int fillchunks = (e + 1023) / 1024;
    int gb2 = gblocks > (fillchunks + 1) / 2 ? gblocks : (fillchunks + 1) / 2;
    fused0_kernel<<<3 * gb2, 256, smem>>>(x, b_gc, src, dst, vals,
                                          n, e, gblocks, fillchunks);

    // 3) standalone gather (8-deep MLP), emits packed bf16 hi/lo agg
    long long gthreads = (long long)n * 32;
    gather_kernel<<<(int)((gthreads + 255) / 256), 256>>>(n);

    // 4) gemm1: out = rownorm(relu(agg) @ W2^T + b2)
    gemm1_kernel<<<gblocks, 256, smem>>>(b2, (float*)d_out, n);
}